// round 12
// baseline (speedup 1.0000x reference)
#include <cuda_runtime.h>
#include <cuda_fp16.h>
#include <math.h>
#include <stdint.h>

#define SEQ   4096
#define BATCH 4
#define NH    24
#define HD    64
#define DIMV  1536
#define N3    4608
#define NT    16384
#define BHN   96

__device__ __align__(16) unsigned short g_X16 [(size_t)NT * DIMV];    // [m][k] fp16
__device__ __align__(16) unsigned short g_WThi[(size_t)N3 * DIMV];    // [n][k] fp16
__device__ __align__(16) unsigned short g_Qhi[(size_t)BHN * SEQ * HD]; // [bh][s][d] (pre-scaled by 0.125*log2e)
__device__ __align__(16) unsigned short g_Khi[(size_t)BHN * SEQ * HD];
__device__ __align__(16) unsigned short g_Vhi[(size_t)BHN * HD * SEQ]; // [bh][d][s]

// ---------------- helpers ----------------
__device__ __forceinline__ void mma16816(float* c, uint32_t a0, uint32_t a1,
                                         uint32_t a2, uint32_t a3,
                                         uint32_t b0, uint32_t b1) {
    asm volatile(
        "mma.sync.aligned.m16n8k16.row.col.f32.f16.f16.f32 "
        "{%0,%1,%2,%3},{%4,%5,%6,%7},{%8,%9},{%0,%1,%2,%3};"
        : "+f"(c[0]), "+f"(c[1]), "+f"(c[2]), "+f"(c[3])
        : "r"(a0), "r"(a1), "r"(a2), "r"(a3), "r"(b0), "r"(b1));
}

#define LDSM4(r0, r1, r2, r3, addr) \
    asm volatile("ldmatrix.sync.aligned.m8n8.x4.shared.b16 {%0,%1,%2,%3}, [%4];" \
        : "=r"(r0), "=r"(r1), "=r"(r2), "=r"(r3) : "r"(addr))

__device__ __forceinline__ uint32_t packh(float a, float b) {
    __half2 h = __floats2half2_rn(a, b);
    return *(uint32_t*)&h;
}

// MUFU exp2 — separate pipe from FMA/tensor, 1 issue slot per exp
__device__ __forceinline__ float ex2(float y) {
    float r;
    asm("ex2.approx.f32 %0, %1;" : "=f"(r) : "f"(y));
    return r;
}

#define CP_ASYNC16(dst, src) \
    asm volatile("cp.async.ca.shared.global [%0], [%1], 16;" :: "r"(dst), "l"(src))
#define CP_COMMIT() asm volatile("cp.async.commit_group;" ::: "memory")
#define CP_WAIT0()  asm volatile("cp.async.wait_group 0;" ::: "memory")

__device__ __forceinline__ uint32_t smem_u32(const void* p) {
    uint32_t a;
    asm("{ .reg .u64 t; cvta.to.shared.u64 t, %1; cvt.u32.u64 %0, t; }" : "=r"(a) : "l"(p));
    return a;
}

// ---------------- Kernel 0a: X -> fp16 (once) ----------------
__global__ __launch_bounds__(256) void x16_prep(const float* __restrict__ X) {
    const size_t i = ((size_t)blockIdx.x * 256 + threadIdx.x) * 8;
    float4 v0 = *(const float4*)&X[i];
    float4 v1 = *(const float4*)&X[i + 4];
    *(uint4*)&g_X16[i] = make_uint4(packh(v0.x, v0.y), packh(v0.z, v0.w),
                                    packh(v1.x, v1.y), packh(v1.z, v1.w));
}

// ---------------- Kernel 0b: W transpose + fp16 ----------------
__global__ __launch_bounds__(256) void wt_prep(const float* __restrict__ W) {
    __shared__ float tile[32][33];
    const int n0 = blockIdx.x * 32, k0 = blockIdx.y * 32;
    const int tx = threadIdx.x & 31, ty = threadIdx.x >> 5;
    for (int r = ty; r < 32; r += 8)
        tile[r][tx] = W[(size_t)(k0 + r) * N3 + n0 + tx];
    __syncthreads();
    for (int r = ty; r < 32; r += 8) {
        g_WThi[(size_t)(n0 + r) * DIMV + k0 + tx] =
            __half_as_ushort(__float2half_rn(tile[tx][r]));
    }
}

// ---------------- Kernel 1: QKV GEMM (fp16 HMMA, cp.async + ldmatrix) -------
#define GA(buf) ((buf) * 10240)
#define GB(buf) (20480 + (buf) * 10240)
#define G_SMEM 66048

__global__ __launch_bounds__(256, 2) void qkv_gemm_mma(
    const float* __restrict__ cosb, const float* __restrict__ sinb,
    const float* __restrict__ bias)
{
    extern __shared__ __align__(16) char smem[];
    const uint32_t sbase = smem_u32(smem);
    const int tid = threadIdx.x, lane = tid & 31, wid = tid >> 5;
    const int g = lane >> 2, t = lane & 3;
    const int wy = wid >> 2, wx = wid & 3;
    const int m0 = blockIdx.y * 128, n0 = blockIdx.x * 128;

    float acc[4][4][4];
#pragma unroll
    for (int i = 0; i < 4; i++)
#pragma unroll
        for (int j = 0; j < 4; j++)
#pragma unroll
            for (int q = 0; q < 4; q++) acc[i][j][q] = 0.f;

    const int arow = tid >> 1, aseg = (tid & 1) * 16;
    const int eo = arow * 40 + aseg;
    const unsigned short* x16row = g_X16 + (size_t)(m0 + arow) * DIMV + aseg;
    const unsigned short* wrow   = g_WThi + (size_t)(n0 + arow) * DIMV + aseg;

    const int mrow = lane & 7, msel = lane >> 3;
    const uint32_t laneA = (((msel & 1) * 8 + mrow) * 40 + (msel >> 1) * 8) * 2;
    const uint32_t laneB = (((msel >> 1) * 8 + mrow) * 40 + (msel & 1) * 8) * 2;

    CP_ASYNC16(sbase + GA(0) + eo * 2,      (const char*)x16row);
    CP_ASYNC16(sbase + GA(0) + eo * 2 + 16, (const char*)(x16row + 8));
    CP_ASYNC16(sbase + GB(0) + eo * 2,      (const char*)wrow);
    CP_ASYNC16(sbase + GB(0) + eo * 2 + 16, (const char*)(wrow + 8));
    CP_COMMIT();
    CP_WAIT0();
    __syncthreads();

    for (int c = 0; c < 48; c++) {
        const int buf = c & 1, nbuf = buf ^ 1;
        if (c + 1 < 48) {
            const unsigned short* xa = x16row + (c + 1) * 32;
            const unsigned short* wb = wrow + (c + 1) * 32;
            CP_ASYNC16(sbase + GA(nbuf) + eo * 2,      (const char*)xa);
            CP_ASYNC16(sbase + GA(nbuf) + eo * 2 + 16, (const char*)(xa + 8));
            CP_ASYNC16(sbase + GB(nbuf) + eo * 2,      (const char*)wb);
            CP_ASYNC16(sbase + GB(nbuf) + eo * 2 + 16, (const char*)(wb + 8));
            CP_COMMIT();
        }

#pragma unroll
        for (int kk = 0; kk < 32; kk += 16) {
            uint32_t aH[4][4], bf[2][4];
#pragma unroll
            for (int mt = 0; mt < 4; mt++)
                LDSM4(aH[mt][0], aH[mt][1], aH[mt][2], aH[mt][3],
                      sbase + GA(buf) + laneA + ((wy * 64 + mt * 16) * 40 + kk) * 2);
#pragma unroll
            for (int hf = 0; hf < 2; hf++)
                LDSM4(bf[hf][0], bf[hf][1], bf[hf][2], bf[hf][3],
                      sbase + GB(buf) + laneB + ((wx * 32 + hf * 16) * 40 + kk) * 2);
#pragma unroll
            for (int nt = 0; nt < 4; nt++) {
                const uint32_t b0 = bf[nt >> 1][(nt & 1) * 2];
                const uint32_t b1 = bf[nt >> 1][(nt & 1) * 2 + 1];
#pragma unroll
                for (int mt = 0; mt < 4; mt++)
                    mma16816(acc[mt][nt], aH[mt][0], aH[mt][1], aH[mt][2], aH[mt][3], b0, b1);
            }
        }

        if (c + 1 < 48) CP_WAIT0();
        __syncthreads();
    }

    // Stage accumulators (stride 129 f32)
    float* st = (float*)smem;
#pragma unroll
    for (int mt = 0; mt < 4; mt++)
#pragma unroll
        for (int nt = 0; nt < 4; nt++) {
            const int r = wy * 64 + mt * 16 + g;
            const int cx = wx * 32 + nt * 8 + 2 * t;
            st[r * 129 + cx]           = acc[mt][nt][0];
            st[r * 129 + cx + 1]       = acc[mt][nt][1];
            st[(r + 8) * 129 + cx]     = acc[mt][nt][2];
            st[(r + 8) * 129 + cx + 1] = acc[mt][nt][3];
        }
    __syncthreads();

    // Epilogue
    const int headSel = tid >> 7, row = tid & 127;
    const int m = m0 + row, b = m >> 12, s = m & (SEQ - 1);
    const int sec = n0 / DIMV, nloc = n0 % DIMV;
    const int h = nloc / HD + headSel;
    const int bh = b * NH + h;
    const int nb = n0 + headSel * 64;

    float v[64];
#pragma unroll
    for (int j = 0; j < 64; j++)
        v[j] = st[row * 129 + headSel * 64 + j] + bias[nb + j];

    if (sec < 2) {
        float ss = 0.f;
#pragma unroll
        for (int j = 0; j < 64; j++) ss = fmaf(v[j], v[j], ss);
        float rinv = rsqrtf(ss * (1.0f / 64.0f) + 1e-6f);
        if (sec == 0) rinv *= 0.18033688011f;   // fold 0.125*log2(e) into Q
        uint32_t ph[32];
#pragma unroll
        for (int i = 0; i < 32; i++) {
            const float cc = cosb[s * HD + 2 * i], sn = sinb[s * HD + 2 * i];
            const float x1 = v[2 * i] * rinv, x2 = v[2 * i + 1] * rinv;
            ph[i] = packh(fmaf(x1, cc, -x2 * sn), fmaf(x2, cc, x1 * sn));
        }
        unsigned short* dh = (sec == 0 ? g_Qhi : g_Khi) + ((size_t)bh * SEQ + s) * HD;
#pragma unroll
        for (int q = 0; q < 8; q++)
            *(uint4*)(dh + q * 8) = make_uint4(ph[4*q], ph[4*q+1], ph[4*q+2], ph[4*q+3]);
    } else {
#pragma unroll
        for (int d = 0; d < 64; d++)
            g_Vhi[((size_t)bh * HD + d) * SEQ + s] =
                __half_as_ushort(__float2half_rn(v[d]));
    }
}

// ---------------- Kernel 2: flash attention (4-stage ring, cross-tile PV) ---
// CTA 256 thr (8 warps x 16 q-rows), 64-key tiles.
// Tile body: QK(kt) + PV(kt-1) back-to-back (independent), softmax(kt) held
// across the barrier. Ring distance: read V((kt-1)&3), write (kt+1)&3.
#define AK(s) ((s) * 9216)
#define AV(s) (36864 + (s) * 9216)
#define A_SMEM 73728

__global__ __launch_bounds__(256, 2) void attn_mma(float* __restrict__ out) {
    extern __shared__ __align__(16) char smem[];
    const uint32_t sbase = smem_u32(smem);
    const int tid = threadIdx.x, lane = tid & 31, wid = tid >> 5;
    const int g = lane >> 2, t = lane & 3;
    const int bh = blockIdx.y, b = bh / NH, h = bh % NH;
    const int q0 = blockIdx.x * 128;

    const int mrow = lane & 7, msel = lane >> 3;
    const uint32_t laneoff = (((msel >> 1) * 8 + mrow) * 72 + (msel & 1) * 8) * 2;

    // Q fragments in registers
    uint32_t qf[4][4];
    {
        const size_t rbase = (size_t)bh * SEQ + q0 + wid * 16;
#pragma unroll
        for (int kq = 0; kq < 4; kq++) {
            const int c0 = kq * 16 + 2 * t, c1 = c0 + 8;
            qf[kq][0] = *(const uint32_t*)&g_Qhi[(rbase + g) * HD + c0];
            qf[kq][1] = *(const uint32_t*)&g_Qhi[(rbase + g + 8) * HD + c0];
            qf[kq][2] = *(const uint32_t*)&g_Qhi[(rbase + g) * HD + c1];
            qf[kq][3] = *(const uint32_t*)&g_Qhi[(rbase + g + 8) * HD + c1];
        }
    }

    float oacc[8][4];
#pragma unroll
    for (int i = 0; i < 8; i++)
#pragma unroll
        for (int j = 0; j < 4; j++) oacc[i][j] = 0.f;
    float rs0 = 0.f, rs1 = 0.f;
    uint32_t paH[8][2];                     // P of previous tile (cross-barrier)

    const int krow = tid >> 2, kseg = (tid & 3) * 16;
    const uint32_t keo = (krow * 72 + kseg) * 2;

    // preload tile 0 into stage 0
    {
        const size_t gk = ((size_t)bh * SEQ + krow) * HD + kseg;
        const size_t gv = ((size_t)bh * HD + krow) * SEQ + kseg;
        CP_ASYNC16(sbase + AK(0) + keo,      (const char*)&g_Khi[gk]);
        CP_ASYNC16(sbase + AK(0) + keo + 16, (const char*)&g_Khi[gk + 8]);
        CP_ASYNC16(sbase + AV(0) + keo,      (const char*)&g_Vhi[gv]);
        CP_ASYNC16(sbase + AV(0) + keo + 16, (const char*)&g_Vhi[gv + 8]);
        CP_COMMIT();
    }

    for (int kt = 0; kt < SEQ / 64; kt++) {
        CP_WAIT0();
        __syncthreads();
        if (kt + 1 < SEQ / 64) {
            const int st = (kt + 1) & 3;
            const size_t gk = ((size_t)bh * SEQ + (kt + 1) * 64 + krow) * HD + kseg;
            const size_t gv = ((size_t)bh * HD + krow) * SEQ + (kt + 1) * 64 + kseg;
            CP_ASYNC16(sbase + AK(st) + keo,      (const char*)&g_Khi[gk]);
            CP_ASYNC16(sbase + AK(st) + keo + 16, (const char*)&g_Khi[gk + 8]);
            CP_ASYNC16(sbase + AV(st) + keo,      (const char*)&g_Vhi[gv]);
            CP_ASYNC16(sbase + AV(st) + keo + 16, (const char*)&g_Vhi[gv + 8]);
            CP_COMMIT();
        }
        const uint32_t kab = sbase + AK(kt & 3) + laneoff;

        // S = Q K^T  (scores pre-scaled: Q carries 0.125*log2e)
        float sacc[8][4];
#pragma unroll
        for (int i = 0; i < 8; i++)
#pragma unroll
            for (int j = 0; j < 4; j++) sacc[i][j] = 0.f;

#pragma unroll
        for (int kq = 0; kq < 4; kq++) {
#pragma unroll
            for (int np = 0; np < 4; np++) {
                uint32_t b0, b1, b2, b3;
                LDSM4(b0, b1, b2, b3, kab + np * 2304 + kq * 32);
                mma16816(sacc[2*np],   qf[kq][0], qf[kq][1], qf[kq][2], qf[kq][3], b0, b1);
                mma16816(sacc[2*np+1], qf[kq][0], qf[kq][1], qf[kq][2], qf[kq][3], b2, b3);
            }
        }

        // O += P(kt-1) V(kt-1)  — independent of QK above; fills softmax gap
        if (kt > 0) {
            const uint32_t vab = sbase + AV((kt - 1) & 3) + laneoff;
#pragma unroll
            for (int k2 = 0; k2 < 4; k2++) {
                const uint32_t aH0 = paH[2*k2][0],   aH1 = paH[2*k2][1];
                const uint32_t aH2 = paH[2*k2+1][0], aH3 = paH[2*k2+1][1];
#pragma unroll
                for (int np = 0; np < 4; np++) {
                    uint32_t b0, b1, b2, b3;
                    LDSM4(b0, b1, b2, b3, vab + np * 2304 + k2 * 32);
                    mma16816(oacc[2*np],   aH0, aH1, aH2, aH3, b0, b1);
                    mma16816(oacc[2*np+1], aH0, aH1, aH2, aH3, b2, b3);
                }
            }
        }

        // Softmax on MUFU (bounded scores: no max pass); result held to kt+1
#pragma unroll
        for (int nt = 0; nt < 8; nt++) {
            const float e0 = ex2(sacc[nt][0]);
            const float e1 = ex2(sacc[nt][1]);
            const float e2 = ex2(sacc[nt][2]);
            const float e3 = ex2(sacc[nt][3]);
            rs0 += e0 + e1;
            rs1 += e2 + e3;
            paH[nt][0] = packh(e0, e1);
            paH[nt][1] = packh(e2, e3);
        }
    }

    // Final PV for the last tile (stage 63&3 = 3; nothing overwrites it)
    {
        const uint32_t vab = sbase + AV((SEQ / 64 - 1) & 3) + laneoff;
#pragma unroll
        for (int k2 = 0; k2 < 4; k2++) {
            const uint32_t aH0 = paH[2*k2][0],   aH1 = paH[2*k2][1];
            const uint32_t aH2 = paH[2*k2+1][0], aH3 = paH[2*k2+1][1];
#pragma unroll
            for (int np = 0; np < 4; np++) {
                uint32_t b0, b1, b2, b3;
                LDSM4(b0, b1, b2, b3, vab + np * 2304 + k2 * 32);
                mma16816(oacc[2*np],   aH0, aH1, aH2, aH3, b0, b1);
                mma16816(oacc[2*np+1], aH0, aH1, aH2, aH3, b2, b3);
            }
        }
    }

    // Quad rowsum reduce, normalize, write
    rs0 += __shfl_xor_sync(0xffffffffu, rs0, 1);
    rs0 += __shfl_xor_sync(0xffffffffu, rs0, 2);
    rs1 += __shfl_xor_sync(0xffffffffu, rs1, 1);
    rs1 += __shfl_xor_sync(0xffffffffu, rs1, 2);
    const float inv0 = 1.0f / rs0, inv1 = 1.0f / rs1;

    const int s0 = q0 + wid * 16 + g, s1 = s0 + 8;
    float* o0 = &out[((size_t)b * SEQ + s0) * DIMV + h * HD];
    float* o1 = &out[((size_t)b * SEQ + s1) * DIMV + h * HD];
#pragma unroll
    for (int nt = 0; nt < 8; nt++) {
        const int cx = nt * 8 + 2 * t;
        *(float2*)(o0 + cx) = make_float2(oacc[nt][0] * inv0, oacc[nt][1] * inv0);
        *(float2*)(o1 + cx) = make_float2(oacc[nt][2] * inv1, oacc[nt][3] * inv1);
    }
}

// ---------------------------------------------------------------------------
extern "C" void kernel_launch(void* const* d_in, const int* in_sizes, int n_in,
                              void* d_out, int out_size) {
    const float* x    = (const float*)d_in[0];
    const float* cosb = (const float*)d_in[1];
    const float* sinb = (const float*)d_in[2];
    const float* w    = (const float*)d_in[3];
    const float* bq   = (const float*)d_in[4];

    cudaFuncSetAttribute(qkv_gemm_mma, cudaFuncAttributeMaxDynamicSharedMemorySize, G_SMEM);
    cudaFuncSetAttribute(attn_mma,     cudaFuncAttributeMaxDynamicSharedMemorySize, A_SMEM);

    x16_prep<<<(NT * DIMV) / (256 * 8), 256>>>(x);
    wt_prep<<<dim3(N3 / 32, DIMV / 32), 256>>>(w);
    qkv_gemm_mma<<<dim3(N3 / 128, NT / 128), 256, G_SMEM>>>(cosb, sinb, bq);
    attn_mma<<<dim3(SEQ / 128, BHN), 256, A_SMEM>>>((float*)d_out);
}

// round 13
// speedup vs baseline: 1.0649x; 1.0649x over previous
#include <cuda_runtime.h>
#include <cuda_fp16.h>
#include <math.h>
#include <stdint.h>

#define SEQ   4096
#define BATCH 4
#define NH    24
#define HD    64
#define DIMV  1536
#define N3    4608
#define NT    16384
#define BHN   96

__device__ __align__(16) unsigned short g_X16 [(size_t)NT * DIMV];    // [m][k] fp16
__device__ __align__(16) unsigned short g_WThi[(size_t)N3 * DIMV];    // [n][k] fp16
__device__ __align__(16) unsigned short g_Qhi[(size_t)BHN * SEQ * HD]; // [bh][s][d] (pre-scaled by 0.125*log2e)
__device__ __align__(16) unsigned short g_Khi[(size_t)BHN * SEQ * HD];
__device__ __align__(16) unsigned short g_Vhi[(size_t)BHN * HD * SEQ]; // [bh][d][s]

// ---------------- helpers ----------------
__device__ __forceinline__ void mma16816(float* c, uint32_t a0, uint32_t a1,
                                         uint32_t a2, uint32_t a3,
                                         uint32_t b0, uint32_t b1) {
    asm volatile(
        "mma.sync.aligned.m16n8k16.row.col.f32.f16.f16.f32 "
        "{%0,%1,%2,%3},{%4,%5,%6,%7},{%8,%9},{%0,%1,%2,%3};"
        : "+f"(c[0]), "+f"(c[1]), "+f"(c[2]), "+f"(c[3])
        : "r"(a0), "r"(a1), "r"(a2), "r"(a3), "r"(b0), "r"(b1));
}

#define LDSM4(r0, r1, r2, r3, addr) \
    asm volatile("ldmatrix.sync.aligned.m8n8.x4.shared.b16 {%0,%1,%2,%3}, [%4];" \
        : "=r"(r0), "=r"(r1), "=r"(r2), "=r"(r3) : "r"(addr))

__device__ __forceinline__ uint32_t packh(float a, float b) {
    __half2 h = __floats2half2_rn(a, b);
    return *(uint32_t*)&h;
}

// MUFU exp2 — separate pipe from FMA/tensor, 1 issue slot per exp
__device__ __forceinline__ float ex2(float y) {
    float r;
    asm("ex2.approx.f32 %0, %1;" : "=f"(r) : "f"(y));
    return r;
}

#define CP_ASYNC16(dst, src) \
    asm volatile("cp.async.ca.shared.global [%0], [%1], 16;" :: "r"(dst), "l"(src))
#define CP_COMMIT() asm volatile("cp.async.commit_group;" ::: "memory")
#define CP_WAIT0()  asm volatile("cp.async.wait_group 0;" ::: "memory")

__device__ __forceinline__ uint32_t smem_u32(const void* p) {
    uint32_t a;
    asm("{ .reg .u64 t; cvta.to.shared.u64 t, %1; cvt.u32.u64 %0, t; }" : "=r"(a) : "l"(p));
    return a;
}

// ---------------- Kernel 0a: X -> fp16 (once) ----------------
__global__ __launch_bounds__(256) void x16_prep(const float* __restrict__ X) {
    const size_t i = ((size_t)blockIdx.x * 256 + threadIdx.x) * 8;
    float4 v0 = *(const float4*)&X[i];
    float4 v1 = *(const float4*)&X[i + 4];
    *(uint4*)&g_X16[i] = make_uint4(packh(v0.x, v0.y), packh(v0.z, v0.w),
                                    packh(v1.x, v1.y), packh(v1.z, v1.w));
}

// ---------------- Kernel 0b: W transpose + fp16 ----------------
__global__ __launch_bounds__(256) void wt_prep(const float* __restrict__ W) {
    __shared__ float tile[32][33];
    const int n0 = blockIdx.x * 32, k0 = blockIdx.y * 32;
    const int tx = threadIdx.x & 31, ty = threadIdx.x >> 5;
    for (int r = ty; r < 32; r += 8)
        tile[r][tx] = W[(size_t)(k0 + r) * N3 + n0 + tx];
    __syncthreads();
    for (int r = ty; r < 32; r += 8) {
        g_WThi[(size_t)(n0 + r) * DIMV + k0 + tx] =
            __half_as_ushort(__float2half_rn(tile[tx][r]));
    }
}

// ---------------- Kernel 1: QKV GEMM (fp16 HMMA, k-chunk 64, stride 72) -----
// CTA 256 thr (8 warps 2x4), tile M=128 x N=128, 24 chunks, 64 HMMAs/sync.
#define GA(buf) ((buf) * 18432)
#define GB(buf) (36864 + (buf) * 18432)
#define G_SMEM 73728              // epilogue staging 128x129 f32 (66048) reuses buffer

__global__ __launch_bounds__(256, 2) void qkv_gemm_mma(
    const float* __restrict__ cosb, const float* __restrict__ sinb,
    const float* __restrict__ bias)
{
    extern __shared__ __align__(16) char smem[];
    const uint32_t sbase = smem_u32(smem);
    const int tid = threadIdx.x, lane = tid & 31, wid = tid >> 5;
    const int g = lane >> 2, t = lane & 3;
    const int wy = wid >> 2, wx = wid & 3;
    const int m0 = blockIdx.y * 128, n0 = blockIdx.x * 128;

    float acc[4][4][4];
#pragma unroll
    for (int i = 0; i < 4; i++)
#pragma unroll
        for (int j = 0; j < 4; j++)
#pragma unroll
            for (int q = 0; q < 4; q++) acc[i][j][q] = 0.f;

    const int arow = tid >> 1, aseg = (tid & 1) * 32;     // 32 elems = 64B per thread
    const int eo = arow * 72 + aseg;
    const unsigned short* x16row = g_X16 + (size_t)(m0 + arow) * DIMV + aseg;
    const unsigned short* wrow   = g_WThi + (size_t)(n0 + arow) * DIMV + aseg;

    const int mrow = lane & 7, msel = lane >> 3;
    const uint32_t laneA = (((msel & 1) * 8 + mrow) * 72 + (msel >> 1) * 8) * 2;
    const uint32_t laneB = (((msel >> 1) * 8 + mrow) * 72 + (msel & 1) * 8) * 2;

    // Prologue: chunk 0 -> buffer 0
#pragma unroll
    for (int u = 0; u < 4; u++) {
        CP_ASYNC16(sbase + GA(0) + (eo + u * 8) * 2, (const char*)(x16row + u * 8));
        CP_ASYNC16(sbase + GB(0) + (eo + u * 8) * 2, (const char*)(wrow + u * 8));
    }
    CP_COMMIT();
    CP_WAIT0();
    __syncthreads();

    for (int c = 0; c < 24; c++) {
        const int buf = c & 1, nbuf = buf ^ 1;
        if (c + 1 < 24) {
            const unsigned short* xa = x16row + (c + 1) * 64;
            const unsigned short* wb = wrow + (c + 1) * 64;
#pragma unroll
            for (int u = 0; u < 4; u++) {
                CP_ASYNC16(sbase + GA(nbuf) + (eo + u * 8) * 2, (const char*)(xa + u * 8));
                CP_ASYNC16(sbase + GB(nbuf) + (eo + u * 8) * 2, (const char*)(wb + u * 8));
            }
            CP_COMMIT();
        }

        // MMA on buffer buf: 4 k16 steps, 64 HMMAs
#pragma unroll
        for (int kk = 0; kk < 64; kk += 16) {
            uint32_t aH[4][4], bf[2][4];
#pragma unroll
            for (int mt = 0; mt < 4; mt++)
                LDSM4(aH[mt][0], aH[mt][1], aH[mt][2], aH[mt][3],
                      sbase + GA(buf) + laneA + ((wy * 64 + mt * 16) * 72 + kk) * 2);
#pragma unroll
            for (int hf = 0; hf < 2; hf++)
                LDSM4(bf[hf][0], bf[hf][1], bf[hf][2], bf[hf][3],
                      sbase + GB(buf) + laneB + ((wx * 32 + hf * 16) * 72 + kk) * 2);
#pragma unroll
            for (int nt = 0; nt < 4; nt++) {
                const uint32_t b0 = bf[nt >> 1][(nt & 1) * 2];
                const uint32_t b1 = bf[nt >> 1][(nt & 1) * 2 + 1];
#pragma unroll
                for (int mt = 0; mt < 4; mt++)
                    mma16816(acc[mt][nt], aH[mt][0], aH[mt][1], aH[mt][2], aH[mt][3], b0, b1);
            }
        }

        if (c + 1 < 24) CP_WAIT0();
        __syncthreads();
    }

    // Stage accumulators (stride 129 f32)
    float* st = (float*)smem;
#pragma unroll
    for (int mt = 0; mt < 4; mt++)
#pragma unroll
        for (int nt = 0; nt < 4; nt++) {
            const int r = wy * 64 + mt * 16 + g;
            const int cx = wx * 32 + nt * 8 + 2 * t;
            st[r * 129 + cx]           = acc[mt][nt][0];
            st[r * 129 + cx + 1]       = acc[mt][nt][1];
            st[(r + 8) * 129 + cx]     = acc[mt][nt][2];
            st[(r + 8) * 129 + cx + 1] = acc[mt][nt][3];
        }
    __syncthreads();

    // Epilogue
    const int headSel = tid >> 7, row = tid & 127;
    const int m = m0 + row, b = m >> 12, s = m & (SEQ - 1);
    const int sec = n0 / DIMV, nloc = n0 % DIMV;
    const int h = nloc / HD + headSel;
    const int bh = b * NH + h;
    const int nb = n0 + headSel * 64;

    float v[64];
#pragma unroll
    for (int j = 0; j < 64; j++)
        v[j] = st[row * 129 + headSel * 64 + j] + bias[nb + j];

    if (sec < 2) {
        float ss = 0.f;
#pragma unroll
        for (int j = 0; j < 64; j++) ss = fmaf(v[j], v[j], ss);
        float rinv = rsqrtf(ss * (1.0f / 64.0f) + 1e-6f);
        if (sec == 0) rinv *= 0.18033688011f;   // fold 0.125*log2(e) into Q
        uint32_t ph[32];
#pragma unroll
        for (int i = 0; i < 32; i++) {
            const float cc = cosb[s * HD + 2 * i], sn = sinb[s * HD + 2 * i];
            const float x1 = v[2 * i] * rinv, x2 = v[2 * i + 1] * rinv;
            ph[i] = packh(fmaf(x1, cc, -x2 * sn), fmaf(x2, cc, x1 * sn));
        }
        unsigned short* dh = (sec == 0 ? g_Qhi : g_Khi) + ((size_t)bh * SEQ + s) * HD;
#pragma unroll
        for (int q = 0; q < 8; q++)
            *(uint4*)(dh + q * 8) = make_uint4(ph[4*q], ph[4*q+1], ph[4*q+2], ph[4*q+3]);
    } else {
#pragma unroll
        for (int d = 0; d < 64; d++)
            g_Vhi[((size_t)bh * HD + d) * SEQ + s] =
                __half_as_ushort(__float2half_rn(v[d]));
    }
}

// ---------------- Kernel 2: flash attention (round-10 exact) ----------------
#define AK(buf) ((buf) * 9216)
#define AV(buf) (18432 + (buf) * 9216)
#define A_SMEM 36864

__global__ __launch_bounds__(256, 2) void attn_mma(float* __restrict__ out) {
    extern __shared__ __align__(16) char smem[];
    const uint32_t sbase = smem_u32(smem);
    const int tid = threadIdx.x, lane = tid & 31, wid = tid >> 5;
    const int g = lane >> 2, t = lane & 3;
    const int bh = blockIdx.y, b = bh / NH, h = bh % NH;
    const int q0 = blockIdx.x * 128;

    const int mrow = lane & 7, msel = lane >> 3;
    const uint32_t laneoff = (((msel >> 1) * 8 + mrow) * 72 + (msel & 1) * 8) * 2;

    // Q fragments in registers
    uint32_t qf[4][4];
    {
        const size_t rbase = (size_t)bh * SEQ + q0 + wid * 16;
#pragma unroll
        for (int kq = 0; kq < 4; kq++) {
            const int c0 = kq * 16 + 2 * t, c1 = c0 + 8;
            qf[kq][0] = *(const uint32_t*)&g_Qhi[(rbase + g) * HD + c0];
            qf[kq][1] = *(const uint32_t*)&g_Qhi[(rbase + g + 8) * HD + c0];
            qf[kq][2] = *(const uint32_t*)&g_Qhi[(rbase + g) * HD + c1];
            qf[kq][3] = *(const uint32_t*)&g_Qhi[(rbase + g + 8) * HD + c1];
        }
    }

    float oacc[8][4];
#pragma unroll
    for (int i = 0; i < 8; i++)
#pragma unroll
        for (int j = 0; j < 4; j++) oacc[i][j] = 0.f;
    float rs0 = 0.f, rs1 = 0.f;

    const int krow = tid >> 2, kseg = (tid & 3) * 16;
    const uint32_t keo = (krow * 72 + kseg) * 2;

    // preload tile 0 into buffer 0
    {
        const size_t gk = ((size_t)bh * SEQ + krow) * HD + kseg;
        const size_t gv = ((size_t)bh * HD + krow) * SEQ + kseg;
        CP_ASYNC16(sbase + AK(0) + keo,      (const char*)&g_Khi[gk]);
        CP_ASYNC16(sbase + AK(0) + keo + 16, (const char*)&g_Khi[gk + 8]);
        CP_ASYNC16(sbase + AV(0) + keo,      (const char*)&g_Vhi[gv]);
        CP_ASYNC16(sbase + AV(0) + keo + 16, (const char*)&g_Vhi[gv + 8]);
        CP_COMMIT();
    }

    for (int kt = 0; kt < SEQ / 64; kt++) {
        CP_WAIT0();
        __syncthreads();
        if (kt + 1 < SEQ / 64) {
            const int nb2 = (kt + 1) & 1;
            const size_t gk = ((size_t)bh * SEQ + (kt + 1) * 64 + krow) * HD + kseg;
            const size_t gv = ((size_t)bh * HD + krow) * SEQ + (kt + 1) * 64 + kseg;
            CP_ASYNC16(sbase + AK(nb2) + keo,      (const char*)&g_Khi[gk]);
            CP_ASYNC16(sbase + AK(nb2) + keo + 16, (const char*)&g_Khi[gk + 8]);
            CP_ASYNC16(sbase + AV(nb2) + keo,      (const char*)&g_Vhi[gv]);
            CP_ASYNC16(sbase + AV(nb2) + keo + 16, (const char*)&g_Vhi[gv + 8]);
            CP_COMMIT();
        }
        const int buf = kt & 1;
        const uint32_t kab = sbase + AK(buf) + laneoff;
        const uint32_t vab = sbase + AV(buf) + laneoff;

        // S = Q K^T  (scores pre-scaled: Q carries 0.125*log2e)
        float sacc[8][4];
#pragma unroll
        for (int i = 0; i < 8; i++)
#pragma unroll
            for (int j = 0; j < 4; j++) sacc[i][j] = 0.f;

#pragma unroll
        for (int kq = 0; kq < 4; kq++) {
#pragma unroll
            for (int np = 0; np < 4; np++) {
                uint32_t b0, b1, b2, b3;
                LDSM4(b0, b1, b2, b3, kab + np * 2304 + kq * 32);
                mma16816(sacc[2*np],   qf[kq][0], qf[kq][1], qf[kq][2], qf[kq][3], b0, b1);
                mma16816(sacc[2*np+1], qf[kq][0], qf[kq][1], qf[kq][2], qf[kq][3], b2, b3);
            }
        }

        // Softmax on MUFU (bounded scores: no max pass), repack P
        uint32_t paH[8][2];
#pragma unroll
        for (int nt = 0; nt < 8; nt++) {
            const float e0 = ex2(sacc[nt][0]);
            const float e1 = ex2(sacc[nt][1]);
            const float e2 = ex2(sacc[nt][2]);
            const float e3 = ex2(sacc[nt][3]);
            rs0 += e0 + e1;
            rs1 += e2 + e3;
            paH[nt][0] = packh(e0, e1);
            paH[nt][1] = packh(e2, e3);
        }

        // O += P V
#pragma unroll
        for (int k2 = 0; k2 < 4; k2++) {
            const uint32_t aH0 = paH[2*k2][0],   aH1 = paH[2*k2][1];
            const uint32_t aH2 = paH[2*k2+1][0], aH3 = paH[2*k2+1][1];
#pragma unroll
            for (int np = 0; np < 4; np++) {
                uint32_t b0, b1, b2, b3;
                LDSM4(b0, b1, b2, b3, vab + np * 2304 + k2 * 32);
                mma16816(oacc[2*np],   aH0, aH1, aH2, aH3, b0, b1);
                mma16816(oacc[2*np+1], aH0, aH1, aH2, aH3, b2, b3);
            }
        }
    }

    // Quad rowsum reduce, normalize, write
    rs0 += __shfl_xor_sync(0xffffffffu, rs0, 1);
    rs0 += __shfl_xor_sync(0xffffffffu, rs0, 2);
    rs1 += __shfl_xor_sync(0xffffffffu, rs1, 1);
    rs1 += __shfl_xor_sync(0xffffffffu, rs1, 2);
    const float inv0 = 1.0f / rs0, inv1 = 1.0f / rs1;

    const int s0 = q0 + wid * 16 + g, s1 = s0 + 8;
    float* o0 = &out[((size_t)b * SEQ + s0) * DIMV + h * HD];
    float* o1 = &out[((size_t)b * SEQ + s1) * DIMV + h * HD];
#pragma unroll
    for (int nt = 0; nt < 8; nt++) {
        const int cx = nt * 8 + 2 * t;
        *(float2*)(o0 + cx) = make_float2(oacc[nt][0] * inv0, oacc[nt][1] * inv0);
        *(float2*)(o1 + cx) = make_float2(oacc[nt][2] * inv1, oacc[nt][3] * inv1);
    }
}

// ---------------------------------------------------------------------------
extern "C" void kernel_launch(void* const* d_in, const int* in_sizes, int n_in,
                              void* d_out, int out_size) {
    const float* x    = (const float*)d_in[0];
    const float* cosb = (const float*)d_in[1];
    const float* sinb = (const float*)d_in[2];
    const float* w    = (const float*)d_in[3];
    const float* bq   = (const float*)d_in[4];

    cudaFuncSetAttribute(qkv_gemm_mma, cudaFuncAttributeMaxDynamicSharedMemorySize, G_SMEM);
    cudaFuncSetAttribute(attn_mma,     cudaFuncAttributeMaxDynamicSharedMemorySize, A_SMEM);

    x16_prep<<<(NT * DIMV) / (256 * 8), 256>>>(x);
    wt_prep<<<dim3(N3 / 32, DIMV / 32), 256>>>(w);
    qkv_gemm_mma<<<dim3(N3 / 128, NT / 128), 256, G_SMEM>>>(cosb, sinb, bq);
    attn_mma<<<dim3(SEQ / 128, BHN), 256, A_SMEM>>>((float*)d_out);
}